// round 1
// baseline (speedup 1.0000x reference)
#include <cuda_runtime.h>

#define NB   256
#define NNEG 1024
#define DD   256
#define DD2  512

// scratch (allocation-free rule: __device__ globals)
__device__ float g_W1t[DD * DD];   // g_W1t[k*DD + j] = W_fc[j*DD2 + k]  (entity half, transposed)
__device__ float g_hn [NB * DD];   // normalized head-side FC output per b
__device__ float g_rp [NB * DD];   // W2 @ re_tail + b_fc per b

// packed fp32x2 FMA (2 MACs per instruction; ptxas never auto-fuses this)
__device__ __forceinline__ float2 ffma2(float2 a, float2 b, float2 c) {
    float2 d;
    asm("fma.rn.f32x2 %0, %1, %2, %3;"
        : "=l"(reinterpret_cast<unsigned long long&>(d))
        : "l"(reinterpret_cast<unsigned long long&>(a)),
          "l"(reinterpret_cast<unsigned long long&>(b)),
          "l"(reinterpret_cast<unsigned long long&>(c)));
    return d;
}

// ---------------------------------------------------------------------------
// Kernel 1: transpose the entity half of W_fc (coalesced loads AND stores)
// ---------------------------------------------------------------------------
__global__ void k_transpose(const float* __restrict__ W) {
    __shared__ float tile[32][33];
    int tx = threadIdx.x, ty = threadIdx.y;
    int j = blockIdx.y * 32 + ty;       // output dim
    int k = blockIdx.x * 32 + tx;       // input dim (entity half: k < 256)
    tile[ty][tx] = W[j * DD2 + k];
    __syncthreads();
    int ko = blockIdx.x * 32 + ty;
    int jo = blockIdx.y * 32 + tx;
    g_W1t[ko * DD + jo] = tile[tx][ty];
}

// ---------------------------------------------------------------------------
// Kernel 2: per-b head pipeline + relation-tail projection
// ---------------------------------------------------------------------------
__global__ void k_prep(const int* __restrict__ head, const int* __restrict__ rel,
                       const float* __restrict__ ent, const float* __restrict__ remb,
                       const float* __restrict__ W,   const float* __restrict__ bfc)
{
    __shared__ float hcat[DD2];    // [entity_emb[head]; re_head]
    __shared__ float rtail[DD];    // re_tail
    __shared__ float hfc[DD];
    __shared__ float red[8];
    __shared__ float invn;

    int b   = blockIdx.x;
    int tid = threadIdx.x;                 // 256 threads
    int hid = head[b];                     // head is [B,1]
    int r   = rel[b];

    hcat[tid]      = ent [(long)hid * DD  + tid];
    hcat[DD + tid] = remb[(long)r  * DD2 + tid];        // re_head = r[:, :256]
    rtail[tid]     = remb[(long)r  * DD2 + DD + tid];   // re_tail = r[:, 256:]
    __syncthreads();

    int wid = tid >> 5, lane = tid & 31;
    // each warp computes 32 consecutive output dims; lanes split k (coalesced W reads)
    for (int jj = 0; jj < 32; jj++) {
        int j = wid * 32 + jj;
        const float* wr = W + (long)j * DD2;
        float aH = 0.f, aT = 0.f;
        #pragma unroll 4
        for (int k = lane; k < DD2; k += 32) aH += wr[k]      * hcat[k];
        #pragma unroll 4
        for (int k = lane; k < DD;  k += 32) aT += wr[DD + k] * rtail[k];
        #pragma unroll
        for (int o = 16; o; o >>= 1) {
            aH += __shfl_xor_sync(0xffffffffu, aH, o);
            aT += __shfl_xor_sync(0xffffffffu, aT, o);
        }
        if (lane == 0) {
            hfc[j] = aH + bfc[j];
            g_rp[b * DD + j] = aT + bfc[j];
        }
    }
    __syncthreads();

    // L2-normalize h_fc
    float v  = hfc[tid];
    float sq = v * v;
    #pragma unroll
    for (int o = 16; o; o >>= 1) sq += __shfl_xor_sync(0xffffffffu, sq, o);
    if (lane == 0) red[wid] = sq;
    __syncthreads();
    if (tid == 0) {
        float s = 0.f;
        #pragma unroll
        for (int i = 0; i < 8; i++) s += red[i];
        invn = 1.0f / fmaxf(sqrtf(s), 1e-12f);
    }
    __syncthreads();
    g_hn[b * DD + tid] = v * invn;
}

// ---------------------------------------------------------------------------
// Kernel 3: fused gathered GEMM + add relproj + L2-normalize + L1 distance
//   block: b = blockIdx.y, 128 tails (blockIdx.x), 512 threads / 16 warps.
//   warp w owns tails w*8..w*8+7; lane owns j in {64p + 2*lane, +1 : p<4}
//   -> a warp covers ALL 256 output dims of its tails => shuffle-only epilogue.
// ---------------------------------------------------------------------------
__global__ void __launch_bounds__(512, 1) k_main(
    const int* __restrict__ tail, const float* __restrict__ ent,
    float* __restrict__ out)
{
    __shared__ float Es[128 * 20];   // entity tile [n][kk], stride 20 (pad)
    __shared__ float Ws[16 * 256];   // W1t tile   [kk][j]
    __shared__ int   tidx[128];

    int b     = blockIdx.y;
    int tile0 = blockIdx.x * 128;
    int tid   = threadIdx.x;
    int w     = tid >> 5, lane = tid & 31;

    if (tid < 128) tidx[tid] = tail[b * NNEG + tile0 + tid];

    float2 acc[8][4];
    #pragma unroll
    for (int i = 0; i < 8; i++)
        #pragma unroll
        for (int p = 0; p < 4; p++) acc[i][p] = make_float2(0.f, 0.f);

    __syncthreads();

    // gather-load mapping: 4 threads per tail, each loads one float4 per tile
    int  n_ld = tid >> 2;
    int  f_ld = (tid & 3) * 4;
    long erow = (long)tidx[n_ld] * DD;

    for (int k0 = 0; k0 < DD; k0 += 16) {
        float4 ev = *(const float4*)(ent + erow + k0 + f_ld);
        float4 wv0, wv1;
        {
            int idx0 = tid,        kk0 = idx0 >> 6, jf0 = (idx0 & 63) * 4;
            int idx1 = tid + 512,  kk1 = idx1 >> 6, jf1 = (idx1 & 63) * 4;
            wv0 = *(const float4*)(g_W1t + (k0 + kk0) * DD + jf0);
            wv1 = *(const float4*)(g_W1t + (k0 + kk1) * DD + jf1);
            __syncthreads();   // previous tile's compute done
            *(float4*)&Es[n_ld * 20 + f_ld] = ev;
            *(float4*)&Ws[kk0 * 256 + jf0]  = wv0;
            *(float4*)&Ws[kk1 * 256 + jf1]  = wv1;
        }
        __syncthreads();

        #pragma unroll
        for (int kk = 0; kk < 16; kk++) {
            float av[8];
            #pragma unroll
            for (int i = 0; i < 8; i++) av[i] = Es[(w * 8 + i) * 20 + kk];
            float2 bv[4];
            #pragma unroll
            for (int p = 0; p < 4; p++)
                bv[p] = *(const float2*)&Ws[kk * 256 + p * 64 + 2 * lane];
            #pragma unroll
            for (int i = 0; i < 8; i++) {
                float2 a2 = make_float2(av[i], av[i]);
                #pragma unroll
                for (int p = 0; p < 4; p++) acc[i][p] = ffma2(a2, bv[p], acc[i][p]);
            }
        }
    }

    // epilogue: t = acc + relproj ; normalize ; score = GAMMA - sum|h_n - t_n|
    const float* rp = g_rp + b * DD;
    const float* hn = g_hn + b * DD;
    float2 rpv[4], hnv[4];
    #pragma unroll
    for (int p = 0; p < 4; p++) {
        rpv[p] = *(const float2*)(rp + p * 64 + 2 * lane);
        hnv[p] = *(const float2*)(hn + p * 64 + 2 * lane);
    }

    #pragma unroll
    for (int i = 0; i < 8; i++) {
        float2 t[4];
        float sq = 0.f;
        #pragma unroll
        for (int p = 0; p < 4; p++) {
            t[p].x = acc[i][p].x + rpv[p].x;
            t[p].y = acc[i][p].y + rpv[p].y;
            sq += t[p].x * t[p].x + t[p].y * t[p].y;
        }
        #pragma unroll
        for (int o = 16; o; o >>= 1) sq += __shfl_xor_sync(0xffffffffu, sq, o);
        float inv = 1.0f / fmaxf(sqrtf(sq), 1e-12f);
        float s = 0.f;
        #pragma unroll
        for (int p = 0; p < 4; p++) {
            s += fabsf(hnv[p].x - t[p].x * inv);
            s += fabsf(hnv[p].y - t[p].y * inv);
        }
        #pragma unroll
        for (int o = 16; o; o >>= 1) s += __shfl_xor_sync(0xffffffffu, s, o);
        if (lane == 0) out[b * NNEG + tile0 + w * 8 + i] = 12.0f - s;
    }
}

// ---------------------------------------------------------------------------
extern "C" void kernel_launch(void* const* d_in, const int* in_sizes, int n_in,
                              void* d_out, int out_size)
{
    const int*   head = (const int*)  d_in[0];
    const int*   tail = (const int*)  d_in[1];
    const int*   rel  = (const int*)  d_in[2];
    const float* ent  = (const float*)d_in[3];
    const float* remb = (const float*)d_in[4];
    const float* W    = (const float*)d_in[5];
    const float* bfc  = (const float*)d_in[6];
    float* out = (float*)d_out;

    k_transpose<<<dim3(8, 8), dim3(32, 32)>>>(W);
    k_prep<<<NB, 256>>>(head, rel, ent, remb, W, bfc);
    k_main<<<dim3(NNEG / 128, NB), 512>>>(tail, ent, out);
}

// round 3
// speedup vs baseline: 2.8101x; 2.8101x over previous
#include <cuda_runtime.h>
#include <cstdint>

#define NB    256
#define NNEG  1024
#define DD    256
#define DD2   512
#define BM    128
#define BK    32
#define STAGES 3
#define AS_FLOATS (BM * 36)                    // 4608 floats (A stage)
#define BS_FLOATS (DD * 36)                    // 9216 floats (B stage)
#define STAGE_FLOATS (AS_FLOATS + BS_FLOATS)   // 13824
#define STAGE_BYTES  (STAGE_FLOATS * 4)        // 55296
#define SMEM_MAIN    (STAGES * STAGE_BYTES)    // 165888

__device__ float g_hn[NB * DD];   // normalized head FC per b
__device__ float g_rp[NB * DD];   // W2 @ re_tail + b_fc per b

#define CP16(d, s) asm volatile("cp.async.cg.shared.global [%0], [%1], 16;" :: "r"(d), "l"(s) : "memory")

__device__ __forceinline__ uint32_t smem_u32(const void* p) {
    uint32_t a;
    asm("{ .reg .u64 t; cvta.to.shared.u64 t, %1; cvt.u32.u64 %0, t; }" : "=r"(a) : "l"(p));
    return a;
}
__device__ __forceinline__ uint32_t f2tf32(float f) {
    uint32_t u;
    asm("cvt.rna.tf32.f32 %0, %1;" : "=r"(u) : "f"(f));
    return u;
}
__device__ __forceinline__ void mma8(float* c, const uint32_t* a, uint32_t b0, uint32_t b1) {
    asm volatile(
        "mma.sync.aligned.m16n8k8.row.col.f32.tf32.tf32.f32 "
        "{%0,%1,%2,%3}, {%4,%5,%6,%7}, {%8,%9}, {%0,%1,%2,%3};"
        : "+f"(c[0]), "+f"(c[1]), "+f"(c[2]), "+f"(c[3])
        : "r"(a[0]), "r"(a[1]), "r"(a[2]), "r"(a[3]), "r"(b0), "r"(b1));
}

// ---------------------------------------------------------------------------
// Kernel 1: per-b head pipeline + relation-tail projection (passed in R1)
// ---------------------------------------------------------------------------
__global__ void k_prep(const int* __restrict__ head, const int* __restrict__ rel,
                       const float* __restrict__ ent, const float* __restrict__ remb,
                       const float* __restrict__ W,   const float* __restrict__ bfc)
{
    __shared__ float hcat[DD2];
    __shared__ float rtail[DD];
    __shared__ float hfc[DD];
    __shared__ float red[8];
    __shared__ float invn;

    int b = blockIdx.x, tid = threadIdx.x;
    int hid = head[b], r = rel[b];

    hcat[tid]      = ent [(long)hid * DD  + tid];
    hcat[DD + tid] = remb[(long)r  * DD2 + tid];
    rtail[tid]     = remb[(long)r  * DD2 + DD + tid];
    __syncthreads();

    int wid = tid >> 5, lane = tid & 31;
    for (int jj = 0; jj < 32; jj++) {
        int j = wid * 32 + jj;
        const float* wr = W + (long)j * DD2;
        float aH = 0.f, aT = 0.f;
        #pragma unroll 4
        for (int k = lane; k < DD2; k += 32) aH += wr[k]      * hcat[k];
        #pragma unroll 4
        for (int k = lane; k < DD;  k += 32) aT += wr[DD + k] * rtail[k];
        #pragma unroll
        for (int o = 16; o; o >>= 1) {
            aH += __shfl_xor_sync(0xffffffffu, aH, o);
            aT += __shfl_xor_sync(0xffffffffu, aT, o);
        }
        if (lane == 0) {
            hfc[j] = aH + bfc[j];
            g_rp[b * DD + j] = aT + bfc[j];
        }
    }
    __syncthreads();

    float v = hfc[tid];
    float sq = v * v;
    #pragma unroll
    for (int o = 16; o; o >>= 1) sq += __shfl_xor_sync(0xffffffffu, sq, o);
    if (lane == 0) red[wid] = sq;
    __syncthreads();
    if (tid == 0) {
        float s = 0.f;
        #pragma unroll
        for (int i = 0; i < 8; i++) s += red[i];
        invn = 1.0f / fmaxf(sqrtf(s), 1e-12f);
    }
    __syncthreads();
    g_hn[b * DD + tid] = v * invn;
}

// ---------------------------------------------------------------------------
// Kernel 2: mma.sync tf32 gathered GEMM + fused normalize/L1 epilogue
//   grid (8, 256): 128 tails/CTA, 256 threads / 8 warps (2m x 4n, 64x64 tiles)
// ---------------------------------------------------------------------------
__global__ void __launch_bounds__(256, 1) k_main(
    const int* __restrict__ tail, const float* __restrict__ ent,
    const float* __restrict__ W, float* __restrict__ out)
{
    extern __shared__ float sm[];
    __shared__ int   tidx[BM];
    __shared__ float rp_s[DD], hn_s[DD];
    __shared__ float sqp[BM][4];
    __shared__ float spp[BM][4];
    __shared__ float invb[BM];

    int tid = threadIdx.x, lane = tid & 31, wid = tid >> 5;
    int b = blockIdx.y, tile0 = blockIdx.x * BM;
    int wm = wid >> 2, wn = wid & 3;
    int lg = lane >> 2, lt = lane & 3;       // groupID, threadID_in_group

    if (tid < BM) tidx[tid] = tail[b * NNEG + tile0 + tid];
    rp_s[tid] = g_rp[b * DD + tid];
    hn_s[tid] = g_hn[b * DD + tid];
    __syncthreads();

    uint32_t sb = smem_u32(sm);

    // producer mapping: seg = 16B segment within a 128B chunk row; groups of 8
    // lanes cover one row's chunk contiguously (coalesced on B, full-line on A).
    int seg = tid & 7;
    int r0  = tid >> 3;                       // 0..31

    float acc[4][8][4];
    #pragma unroll
    for (int i = 0; i < 4; i++)
        #pragma unroll
        for (int t = 0; t < 8; t++)
            #pragma unroll
            for (int q = 0; q < 4; q++) acc[i][t][q] = 0.f;

    // ---- pipelined mainloop ----
    #define ISSUE(c) do {                                                       \
        uint32_t _st = sb + (uint32_t)((c) % STAGES) * STAGE_BYTES;             \
        _Pragma("unroll")                                                       \
        for (int _i = 0; _i < 4; _i++) {                                        \
            int _r = r0 + 32 * _i;                                              \
            const float* _src = ent + (long)tidx[_r] * DD + (c) * BK + seg * 4; \
            CP16(_st + (uint32_t)(_r * 144 + seg * 16), _src);                  \
        }                                                                       \
        _Pragma("unroll")                                                       \
        for (int _i = 0; _i < 8; _i++) {                                        \
            int _r = r0 + 32 * _i;                                              \
            const float* _src = W + (long)_r * DD2 + (c) * BK + seg * 4;        \
            CP16(_st + (uint32_t)(18432 + _r * 144 + seg * 16), _src);          \
        }                                                                       \
        asm volatile("cp.async.commit_group;" ::: "memory");                    \
    } while (0)

    ISSUE(0);
    ISSUE(1);

    #pragma unroll
    for (int c = 0; c < 8; c++) {
        if (c < 7) asm volatile("cp.async.wait_group 1;" ::: "memory");
        else       asm volatile("cp.async.wait_group 0;" ::: "memory");
        __syncthreads();
        if (c + 2 < 8) ISSUE(c + 2);

        const float* Asp = sm + (c % STAGES) * STAGE_FLOATS;
        const float* Bsp = Asp + AS_FLOATS;

        #pragma unroll
        for (int ks = 0; ks < 4; ks++) {
            int k0 = ks * 8 + lt;
            uint32_t a[4][4];
            #pragma unroll
            for (int i = 0; i < 4; i++) {
                int r = wm * 64 + i * 16 + lg;
                a[i][0] = f2tf32(Asp[r * 36 + k0]);
                a[i][1] = f2tf32(Asp[(r + 8) * 36 + k0]);
                a[i][2] = f2tf32(Asp[r * 36 + k0 + 4]);
                a[i][3] = f2tf32(Asp[(r + 8) * 36 + k0 + 4]);
            }
            #pragma unroll
            for (int t = 0; t < 8; t++) {
                int n = wn * 64 + t * 8 + lg;
                uint32_t b0 = f2tf32(Bsp[n * 36 + k0]);
                uint32_t b1 = f2tf32(Bsp[n * 36 + k0 + 4]);
                #pragma unroll
                for (int i = 0; i < 4; i++) mma8(acc[i][t], a[i], b0, b1);
            }
        }
    }
    #undef ISSUE

    // ---- epilogue (all in registers; tiny smem reductions) ----
    // pass 1: sq per row
    #pragma unroll
    for (int i = 0; i < 4; i++) {
        #pragma unroll
        for (int rh = 0; rh < 2; rh++) {
            float s = 0.f;
            #pragma unroll
            for (int t = 0; t < 8; t++) {
                int n0 = wn * 64 + t * 8 + 2 * lt;
                float c0 = acc[i][t][rh * 2 + 0] + rp_s[n0];
                float c1 = acc[i][t][rh * 2 + 1] + rp_s[n0 + 1];
                s += c0 * c0 + c1 * c1;
            }
            s += __shfl_xor_sync(0xffffffffu, s, 1);
            s += __shfl_xor_sync(0xffffffffu, s, 2);
            if (lt == 0) sqp[wm * 64 + i * 16 + rh * 8 + lg][wn] = s;
        }
    }
    __syncthreads();
    if (tid < BM) {
        float sq = sqp[tid][0] + sqp[tid][1] + sqp[tid][2] + sqp[tid][3];
        invb[tid] = 1.0f / fmaxf(sqrtf(sq), 1e-12f);
    }
    __syncthreads();

    // pass 2: L1 distance per row
    #pragma unroll
    for (int i = 0; i < 4; i++) {
        #pragma unroll
        for (int rh = 0; rh < 2; rh++) {
            int row = wm * 64 + i * 16 + rh * 8 + lg;
            float inv = invb[row];
            float s = 0.f;
            #pragma unroll
            for (int t = 0; t < 8; t++) {
                int n0 = wn * 64 + t * 8 + 2 * lt;
                float t0 = (acc[i][t][rh * 2 + 0] + rp_s[n0])     * inv;
                float t1 = (acc[i][t][rh * 2 + 1] + rp_s[n0 + 1]) * inv;
                s += fabsf(hn_s[n0] - t0) + fabsf(hn_s[n0 + 1] - t1);
            }
            s += __shfl_xor_sync(0xffffffffu, s, 1);
            s += __shfl_xor_sync(0xffffffffu, s, 2);
            if (lt == 0) spp[row][wn] = s;
        }
    }
    __syncthreads();
    if (tid < BM)
        out[b * NNEG + tile0 + tid] =
            12.0f - (spp[tid][0] + spp[tid][1] + spp[tid][2] + spp[tid][3]);
}

// ---------------------------------------------------------------------------
extern "C" void kernel_launch(void* const* d_in, const int* in_sizes, int n_in,
                              void* d_out, int out_size)
{
    const int*   head = (const int*)  d_in[0];
    const int*   tail = (const int*)  d_in[1];
    const int*   rel  = (const int*)  d_in[2];
    const float* ent  = (const float*)d_in[3];
    const float* remb = (const float*)d_in[4];
    const float* W    = (const float*)d_in[5];
    const float* bfc  = (const float*)d_in[6];
    float* out = (float*)d_out;

    cudaFuncSetAttribute(k_main, cudaFuncAttributeMaxDynamicSharedMemorySize, SMEM_MAIN);

    k_prep<<<NB, 256>>>(head, rel, ent, remb, W, bfc);
    k_main<<<dim3(NNEG / BM, NB), 256, SMEM_MAIN>>>(tail, ent, W, out);
}